// round 12
// baseline (speedup 1.0000x reference)
#include <cuda_runtime.h>
#include <cuda_bf16.h>
#include <cuda_fp8.h>

#define N_NODES 8192
#define N_EDGES 131072
#define FEAT    512
#define HID     256
#define OUTD    1792     // (2^(K+1)-1)*HID
#define NGRAPH  64
#define WORDS   256      // 8192 / 32 bits
#define A1CAP   128      // per-row 1-hop cap (max degree ~45)
#define A2CAP   1536     // per-row 2-hop cap (max ~400)
#define ROWB    (OUTD * 2)   // bytes per bf16 mirror row
#define FP8SCL  16.0f        // exponent shift into e4m3 normal range

// ---------------- device scratch (no allocations allowed) ----------------
__device__ unsigned g_Abit [N_NODES * WORDS];   // raw binarized adjacency (8 MB)
__device__ int      g_selfcnt[N_NODES];
__device__ float    g_dinv1[N_NODES];
__device__ float    g_dinv2[N_NODES];
__device__ unsigned short g_idx1[N_NODES * A1CAP];          // A1 CSR node indices
__device__ int      g_cnt1[N_NODES];
__device__ unsigned short g_idx2[(size_t)N_NODES * A2CAP];  // A2 CSR node indices
__device__ int      g_cnt2[N_NODES];
__device__ float    g_h[(size_t)N_NODES * OUTD];           // fp32 h_node (56 MB)
__device__ __nv_bfloat16 g_hb1[(size_t)N_NODES * OUTD];    // bf16 dinv1-scaled (A1 gathers)
__device__ unsigned char g_hb2[(size_t)N_NODES * OUTD];    // e4m3 16*dinv2-scaled (A2 gathers)
__device__ float    g_pool[NGRAPH * OUTD];
__device__ int      g_gcnt[NGRAPH];
__device__ int      g_e64, g_b64;               // truthy => int64 layout

__device__ __forceinline__ int geti(const void* p, int i, int is64) {
    return is64 ? (int)((const long long*)p)[i] : ((const int*)p)[i];
}

__device__ __forceinline__ float2 fp8x2_to_float2(unsigned short s) {
    __half2_raw hr = __nv_cvt_fp8x2_to_halfraw2(s, __NV_E4M3);
    return __half22float2(*reinterpret_cast<__half2*>(&hr));
}
__device__ __forceinline__ unsigned short float2_to_fp8x2(float a, float b) {
    return __nv_cvt_float2_to_fp8x2(make_float2(a, b), __NV_SATFINITE, __NV_E4M3);
}

// ---------------- dtype detection (parallel) ----------------
__global__ void k_detect(const int* __restrict__ w, int nwords, int* flag) {
    int stride = 2 * gridDim.x * blockDim.x;
    int any = 0;
    for (int k = 1 + 2 * (int)(blockIdx.x * blockDim.x + threadIdx.x);
         k < nwords; k += stride)
        any |= w[k];
    if (__syncthreads_or(any) && threadIdx.x == 0)
        atomicAnd(flag, 0);
}

// ---------------- build raw adjacency bitmask ----------------
__global__ void k_edges(const void* __restrict__ e, const int* __restrict__ e64flag) {
    int i = blockIdx.x * blockDim.x + threadIdx.x;
    if (i >= N_EDGES) return;
    int is64 = *e64flag;
    int r = geti(e, i, is64);
    int c = geti(e, N_EDGES + i, is64);
    atomicOr(&g_Abit[r * WORDS + (c >> 5)], 1u << (c & 31));
    if (r == c) atomicAdd(&g_selfcnt[r], 1);
}

// Warp-shuffle block scan over per-word popcounts; extract set bits (ascending).
template <typename T>
__device__ __forceinline__ int scan_extract(unsigned m, int t, int* s_warp,
                                            T* dst, int cap, int* tot) {
    int lane = t & 31, wid = t >> 5;
    int pc = __popc(m);
    int x = pc;
#pragma unroll
    for (int off = 1; off < 32; off <<= 1) {
        int v = __shfl_up_sync(0xffffffffu, x, off);
        if (lane >= off) x += v;
    }
    if (lane == 31) s_warp[wid] = x;
    __syncthreads();
    int base = 0, total = 0;
#pragma unroll
    for (int w = 0; w < 8; w++) {
        int s = s_warp[w];
        if (w < wid) base += s;
        total += s;
    }
    int o = base + x - pc;
    unsigned mm = m;
    while (mm) {
        int b = __ffs(mm) - 1; mm &= mm - 1;
        if (o < cap) dst[o] = (T)(t * 32 + b);
        o++;
    }
    __syncthreads();
    *tot = total;
    return total < cap ? total : cap;
}

// ---------------- A2 build + CSR (u16 indices) + degrees ----------------
__global__ __launch_bounds__(256) void k_a2() {
    int i = blockIdx.x, t = threadIdx.x;
    __shared__ int   s_warp[8];
    __shared__ int   s_raw[128];
    __shared__ uint4 s_acc[4][64];
    __shared__ int   s_diag;

    unsigned w = g_Abit[i * WORDS + t];
    int tot_raw;
    int cnt_raw = scan_extract<int>(w, t, s_warp, s_raw, 128, &tot_raw);

    // neighbor-OR with uint4 loads: subgroup sg handles neighbors sg, sg+4, ...
    int wg = t & 63, sg = t >> 6;
    uint4 acc4 = make_uint4(0, 0, 0, 0);
    for (int n = sg; n < cnt_raw; n += 4) {
        uint4 v = *(const uint4*)&g_Abit[s_raw[n] * WORDS + wg * 4];
        acc4.x |= v.x; acc4.y |= v.y; acc4.z |= v.z; acc4.w |= v.w;
    }
    s_acc[sg][wg] = acc4;
    __syncthreads();
    const unsigned* flat = (const unsigned*)&s_acc[0][0];
    unsigned accw = flat[t] | flat[256 + t] | flat[512 + t] | flat[768 + t];

    unsigned dm = (t == (i >> 5)) ? (1u << (i & 31)) : 0u;
    unsigned a2 = accw & ~w & ~dm;

    // diagonal removal rule for A1: (A - I) > 0 keeps diag only if selfcnt >= 2
    if (t == (i >> 5))
        s_diag = ((w & (1u << (i & 31))) && g_selfcnt[i] < 2) ? 1 : 0;
    __syncthreads();
    int remove = s_diag;

    // A1 CSR directly from the raw neighbor list
    if (t < cnt_raw) {
        int j = s_raw[t];
        int pos = t;
        if (remove) {
            if (j == i) pos = -1;
            else if (j > i) pos = t - 1;
        }
        if (pos >= 0 && pos < A1CAP)
            g_idx1[i * A1CAP + pos] = (unsigned short)j;
    }
    int tot1 = tot_raw - remove;

    int tot2;
    int c2 = scan_extract<unsigned short>(a2, t, s_warp,
                                          &g_idx2[(size_t)i * A2CAP], A2CAP, &tot2);

    if (t == 0) {
        g_cnt1[i] = tot1 < A1CAP ? tot1 : A1CAP;
        g_cnt2[i] = c2;
        g_dinv1[i] = tot1 > 0 ? rsqrtf((float)tot1) : 0.f;
        g_dinv2[i] = tot2 > 0 ? rsqrtf((float)tot2) : 0.f;
    }
}

// ---------------- embed: r = relu(x @ w_embed) -> g_h / scaled mirrors ----------------
// 128x128 tile, BK=32, 256 threads, 8x8 per thread.
__global__ __launch_bounds__(256) void k_embed(const float* __restrict__ X,
                                               const float* __restrict__ W) {
    __shared__ float As[32][128 + 4];
    __shared__ float Bs[32][128 + 4];
    int bm = blockIdx.x * 128;
    int bn = blockIdx.y * 128;
    int tid = threadIdx.x;
    int tr = tid >> 4, tc = tid & 15;
    float acc[8][8] = {};
    for (int k0 = 0; k0 < FEAT; k0 += 32) {
#pragma unroll
        for (int q = 0; q < 4; q++) {
            int idx = tid * 4 + q;
            int m  = idx >> 3;
            int kg = (idx & 7) * 4;
            float4 v = *(const float4*)(X + (size_t)(bm + m) * FEAT + k0 + kg);
            As[kg + 0][m] = v.x; As[kg + 1][m] = v.y;
            As[kg + 2][m] = v.z; As[kg + 3][m] = v.w;
        }
#pragma unroll
        for (int q = 0; q < 4; q++) {
            int idx = tid * 4 + q;
            int k  = idx >> 5;
            int ng = (idx & 31) * 4;
            float4 v = *(const float4*)(W + (size_t)(k0 + k) * HID + bn + ng);
            *(float4*)&Bs[k][ng] = v;
        }
        __syncthreads();
#pragma unroll
        for (int kk = 0; kk < 32; kk++) {
            float a[8], b[8];
#pragma unroll
            for (int p = 0; p < 8; p++) a[p] = As[kk][tr * 8 + p];
#pragma unroll
            for (int q = 0; q < 8; q++) b[q] = Bs[kk][tc * 8 + q];
#pragma unroll
            for (int p = 0; p < 8; p++)
#pragma unroll
                for (int q = 0; q < 8; q++)
                    acc[p][q] += a[p] * b[q];
        }
        __syncthreads();
    }
#pragma unroll
    for (int p = 0; p < 8; p++) {
        int row = bm + tr * 8 + p;
        float d1 = g_dinv1[row];
        float s2 = FP8SCL * g_dinv2[row];
        size_t o = (size_t)row * OUTD + bn + tc * 8;
        float r[8];
#pragma unroll
        for (int q = 0; q < 8; q++) {
            float v = acc[p][q];
            r[q] = v > 0.f ? v : 0.f;
            g_h[o + q]   = r[q];
            g_hb1[o + q] = __float2bfloat16_rn(d1 * r[q]);
        }
        uint2 m2;
        m2.x = (unsigned)float2_to_fp8x2(s2 * r[0], s2 * r[1])
             | ((unsigned)float2_to_fp8x2(s2 * r[2], s2 * r[3]) << 16);
        m2.y = (unsigned)float2_to_fp8x2(s2 * r[4], s2 * r[5])
             | ((unsigned)float2_to_fp8x2(s2 * r[6], s2 * r[7]) << 16);
        *(uint2*)&g_hb2[o] = m2;
    }
}

// ---------------- SpMM from CSR: 8 cols/thread, u16 smem staging ----------------
// grid (_, 2): y=0 -> A1 (bf16 LDG.128), y=1 -> A2 (fp8 LDG.64). 64 threads.
// two_rows: warp w handles row bx*2+w with per-warp staging (full occupancy).
__global__ __launch_bounds__(64) void k_spmm(int in_off, int out_off1, int out_off2,
                                             int write_mirror, int two_rows) {
    __shared__ __align__(8) unsigned short s_j[2 * A2CAP];
    int t = threadIdx.x, y = blockIdx.y;
    int row, colt;
    unsigned short* sj;
    if (two_rows) { row = blockIdx.x * 2 + (t >> 5); colt = t & 31; sj = s_j + (t >> 5) * A2CAP; }
    else          { row = blockIdx.x;                colt = t;      sj = s_j; }

    float a0[8] = {}, a1[8] = {}, a2[8] = {}, a3[8] = {};
    float di;
    int out_off;
    const unsigned short* idx;
    int cnt;

    if (y == 0) { idx = &g_idx1[row * A1CAP];          cnt = g_cnt1[row];
                  di = g_dinv1[row];                   out_off = out_off1; }
    else        { idx = &g_idx2[(size_t)row * A2CAP];  cnt = g_cnt2[row];
                  di = g_dinv2[row] * (1.0f / FP8SCL); out_off = out_off2; }

    if (two_rows) {
        int lane = t & 31;
        for (int k = lane; k < cnt; k += 32) sj[k] = idx[k];
        __syncwarp();
    } else {
        for (int k = t; k < cnt; k += 64) sj[k] = idx[k];
        __syncthreads();
    }

    if (y == 0) {          // ---- A1: bf16 gathers, stride ROWB ----
        const char* base = (const char*)g_hb1 + 2 * in_off + 16 * colt;
        int n = 0;
        for (; n + 3 < cnt; n += 4) {
            ushort4 j4 = *(const ushort4*)&sj[n];
            uint4 u0 = *(const uint4*)(base + (int)j4.x * ROWB);
            uint4 u1 = *(const uint4*)(base + (int)j4.y * ROWB);
            uint4 u2 = *(const uint4*)(base + (int)j4.z * ROWB);
            uint4 u3 = *(const uint4*)(base + (int)j4.w * ROWB);
#pragma unroll
            for (int q = 0; q < 4; q++) {
                float2 v; unsigned w;
                w = (&u0.x)[q]; v = __bfloat1622float2(*reinterpret_cast<__nv_bfloat162*>(&w));
                a0[2 * q] += v.x; a0[2 * q + 1] += v.y;
                w = (&u1.x)[q]; v = __bfloat1622float2(*reinterpret_cast<__nv_bfloat162*>(&w));
                a1[2 * q] += v.x; a1[2 * q + 1] += v.y;
                w = (&u2.x)[q]; v = __bfloat1622float2(*reinterpret_cast<__nv_bfloat162*>(&w));
                a2[2 * q] += v.x; a2[2 * q + 1] += v.y;
                w = (&u3.x)[q]; v = __bfloat1622float2(*reinterpret_cast<__nv_bfloat162*>(&w));
                a3[2 * q] += v.x; a3[2 * q + 1] += v.y;
            }
        }
        for (; n < cnt; n++) {
            uint4 u = *(const uint4*)(base + (int)sj[n] * ROWB);
#pragma unroll
            for (int q = 0; q < 4; q++) {
                unsigned w = (&u.x)[q];
                float2 v = __bfloat1622float2(*reinterpret_cast<__nv_bfloat162*>(&w));
                a0[2 * q] += v.x; a0[2 * q + 1] += v.y;
            }
        }
    } else {               // ---- A2: fp8 gathers, stride OUTD ----
        const char* base = (const char*)g_hb2 + in_off + 8 * colt;
        int n = 0;
        for (; n + 7 < cnt; n += 8) {
            ushort4 ja = *(const ushort4*)&sj[n];
            ushort4 jb = *(const ushort4*)&sj[n + 4];
            uint2 u0 = *(const uint2*)(base + (int)ja.x * OUTD);
            uint2 u1 = *(const uint2*)(base + (int)ja.y * OUTD);
            uint2 u2 = *(const uint2*)(base + (int)ja.z * OUTD);
            uint2 u3 = *(const uint2*)(base + (int)ja.w * OUTD);
            uint2 u4 = *(const uint2*)(base + (int)jb.x * OUTD);
            uint2 u5 = *(const uint2*)(base + (int)jb.y * OUTD);
            uint2 u6 = *(const uint2*)(base + (int)jb.z * OUTD);
            uint2 u7 = *(const uint2*)(base + (int)jb.w * OUTD);
#pragma unroll
            for (int q = 0; q < 2; q++) {
                unsigned w; float2 v;
                w = (&u0.x)[q];
                v = fp8x2_to_float2((unsigned short)w);
                a0[4 * q] += v.x; a0[4 * q + 1] += v.y;
                v = fp8x2_to_float2((unsigned short)(w >> 16));
                a0[4 * q + 2] += v.x; a0[4 * q + 3] += v.y;
                w = (&u1.x)[q];
                v = fp8x2_to_float2((unsigned short)w);
                a1[4 * q] += v.x; a1[4 * q + 1] += v.y;
                v = fp8x2_to_float2((unsigned short)(w >> 16));
                a1[4 * q + 2] += v.x; a1[4 * q + 3] += v.y;
                w = (&u2.x)[q];
                v = fp8x2_to_float2((unsigned short)w);
                a2[4 * q] += v.x; a2[4 * q + 1] += v.y;
                v = fp8x2_to_float2((unsigned short)(w >> 16));
                a2[4 * q + 2] += v.x; a2[4 * q + 3] += v.y;
                w = (&u3.x)[q];
                v = fp8x2_to_float2((unsigned short)w);
                a3[4 * q] += v.x; a3[4 * q + 1] += v.y;
                v = fp8x2_to_float2((unsigned short)(w >> 16));
                a3[4 * q + 2] += v.x; a3[4 * q + 3] += v.y;
                w = (&u4.x)[q];
                v = fp8x2_to_float2((unsigned short)w);
                a0[4 * q] += v.x; a0[4 * q + 1] += v.y;
                v = fp8x2_to_float2((unsigned short)(w >> 16));
                a0[4 * q + 2] += v.x; a0[4 * q + 3] += v.y;
                w = (&u5.x)[q];
                v = fp8x2_to_float2((unsigned short)w);
                a1[4 * q] += v.x; a1[4 * q + 1] += v.y;
                v = fp8x2_to_float2((unsigned short)(w >> 16));
                a1[4 * q + 2] += v.x; a1[4 * q + 3] += v.y;
                w = (&u6.x)[q];
                v = fp8x2_to_float2((unsigned short)w);
                a2[4 * q] += v.x; a2[4 * q + 1] += v.y;
                v = fp8x2_to_float2((unsigned short)(w >> 16));
                a2[4 * q + 2] += v.x; a2[4 * q + 3] += v.y;
                w = (&u7.x)[q];
                v = fp8x2_to_float2((unsigned short)w);
                a3[4 * q] += v.x; a3[4 * q + 1] += v.y;
                v = fp8x2_to_float2((unsigned short)(w >> 16));
                a3[4 * q + 2] += v.x; a3[4 * q + 3] += v.y;
            }
        }
        for (; n < cnt; n++) {
            uint2 u = *(const uint2*)(base + (int)sj[n] * OUTD);
#pragma unroll
            for (int q = 0; q < 2; q++) {
                unsigned w = (&u.x)[q];
                float2 v = fp8x2_to_float2((unsigned short)w);
                a0[4 * q] += v.x; a0[4 * q + 1] += v.y;
                v = fp8x2_to_float2((unsigned short)(w >> 16));
                a0[4 * q + 2] += v.x; a0[4 * q + 3] += v.y;
            }
        }
    }

    float r[8];
#pragma unroll
    for (int q = 0; q < 8; q++) {
        float v = di * ((a0[q] + a1[q]) + (a2[q] + a3[q]));
        r[q] = v > 0.f ? v : 0.f;
    }
    size_t ob = (size_t)row * OUTD + out_off + 8 * colt;
    *(float4*)&g_h[ob]     = make_float4(r[0], r[1], r[2], r[3]);
    *(float4*)&g_h[ob + 4] = make_float4(r[4], r[5], r[6], r[7]);
    if (write_mirror) {
        float d1 = g_dinv1[row];
        float s2 = FP8SCL * g_dinv2[row];
        uint4 m1;
#pragma unroll
        for (int q = 0; q < 4; q++) {
            __nv_bfloat162 b1 = __float22bfloat162_rn(
                make_float2(d1 * r[2 * q], d1 * r[2 * q + 1]));
            (&m1.x)[q] = *reinterpret_cast<unsigned*>(&b1);
        }
        *(uint4*)&g_hb1[ob] = m1;
        uint2 m2;
        m2.x = (unsigned)float2_to_fp8x2(s2 * r[0], s2 * r[1])
             | ((unsigned)float2_to_fp8x2(s2 * r[2], s2 * r[3]) << 16);
        m2.y = (unsigned)float2_to_fp8x2(s2 * r[4], s2 * r[5])
             | ((unsigned)float2_to_fp8x2(s2 * r[6], s2 * r[7]) << 16);
        *(uint2*)&g_hb2[ob] = m2;
    }
}

// ---------------- graph sizes ----------------
__global__ void k_count(const void* __restrict__ batch, const int* __restrict__ b64flag) {
    int i = blockIdx.x * blockDim.x + threadIdx.x;
    if (i < N_NODES) atomicAdd(&g_gcnt[geti(batch, i, *b64flag)], 1);
}

// ---------------- segment-sum pool (batch is sorted), float4 ----------------
__global__ __launch_bounds__(224) void k_pool(const void* __restrict__ batch,
                                              const int* __restrict__ b64flag) {
    int is64 = *b64flag;
    int n0 = blockIdx.x * 128;
    int c  = (blockIdx.y * 224 + threadIdx.x) * 4;
    float4 acc = {0.f, 0.f, 0.f, 0.f};
    int cur = geti(batch, n0, is64);
    for (int n = n0; n < n0 + 128; n++) {
        int b = geti(batch, n, is64);
        if (b != cur) {
            float* p = &g_pool[cur * OUTD + c];
            atomicAdd(p + 0, acc.x); atomicAdd(p + 1, acc.y);
            atomicAdd(p + 2, acc.z); atomicAdd(p + 3, acc.w);
            acc = make_float4(0.f, 0.f, 0.f, 0.f);
            cur = b;
        }
        float4 v = *(const float4*)&g_h[(size_t)n * OUTD + c];
        acc.x += v.x; acc.y += v.y; acc.z += v.z; acc.w += v.w;
    }
    float* p = &g_pool[cur * OUTD + c];
    atomicAdd(p + 0, acc.x); atomicAdd(p + 1, acc.y);
    atomicAdd(p + 2, acc.z); atomicAdd(p + 3, acc.w);
}

// ---------------- final: (pool/cnt) @ W_out + b_out ; tail = loss = 0 ----------------
// grid (NGRAPH, 2), 128 threads: each block computes 128 output columns.
__global__ __launch_bounds__(128) void k_out(const float* __restrict__ Wout,
                                             const float* __restrict__ bout,
                                             float* __restrict__ out, int out_size) {
    int g = blockIdx.x, t = threadIdx.x;
    int h = blockIdx.y * 128 + t;
    __shared__ float sg[OUTD];
    float inv = 1.0f / fmaxf((float)g_gcnt[g], 1.0f);
    for (int k = t; k < OUTD; k += 128)
        sg[k] = g_pool[g * OUTD + k] * inv;
    __syncthreads();
    float acc = bout[h];
#pragma unroll 8
    for (int k = 0; k < OUTD; k++)
        acc += sg[k] * Wout[(size_t)k * HID + h];
    int oi = g * HID + h;
    if (oi < out_size) out[oi] = acc;
    if (g == 0 && blockIdx.y == 0) {
        for (int idx = NGRAPH * HID + t; idx < out_size; idx += 128)
            out[idx] = 0.f;
    }
}

// ---------------- launcher ----------------
extern "C" void kernel_launch(void* const* d_in, const int* in_sizes, int n_in,
                              void* d_out, int out_size) {
    const float* x       = (const float*)d_in[0];
    const void*  e       = d_in[1];
    const void*  batch   = d_in[2];
    const float* w_embed = (const float*)d_in[3];
    const float* W_out   = (const float*)d_in[4];
    const float* b_out   = (const float*)d_in[5];
    float* out = (float*)d_out;

    void *pA, *pSelf, *pPool, *pGcnt, *pE64, *pB64;
    cudaGetSymbolAddress(&pA,    g_Abit);
    cudaGetSymbolAddress(&pSelf, g_selfcnt);
    cudaGetSymbolAddress(&pPool, g_pool);
    cudaGetSymbolAddress(&pGcnt, g_gcnt);
    cudaGetSymbolAddress(&pE64,  g_e64);
    cudaGetSymbolAddress(&pB64,  g_b64);

    cudaMemsetAsync(pA,    0, sizeof(unsigned) * N_NODES * WORDS);
    cudaMemsetAsync(pSelf, 0, sizeof(int)   * N_NODES);
    cudaMemsetAsync(pPool, 0, sizeof(float) * NGRAPH * OUTD);
    cudaMemsetAsync(pGcnt, 0, sizeof(int)   * NGRAPH);
    cudaMemsetAsync(pE64,  1, sizeof(int));   // truthy "int64" default
    cudaMemsetAsync(pB64,  1, sizeof(int));

    k_detect<<<64, 256>>>((const int*)e,     2 * N_EDGES, (int*)pE64);
    k_detect<<<64, 256>>>((const int*)batch, N_NODES,     (int*)pB64);

    k_edges<<<(N_EDGES + 255) / 256, 256>>>(e, (const int*)pE64);
    k_a2<<<N_NODES, 256>>>();
    k_embed<<<dim3(N_NODES / 128, HID / 128), 256>>>(x, w_embed);

    // hop 1: in = cols [0,256) -> A1 out [256,512), A2 out [512,768). 2 rows/block.
    k_spmm<<<dim3(N_NODES / 2, 2), 64>>>(0, HID, 2 * HID, 1, 1);
    // hop 2: in = cols [256,768) -> A1 out [768,1280), A2 out [1280,1792)
    k_spmm<<<dim3(N_NODES, 2), 64>>>(HID, 3 * HID, 5 * HID, 0, 0);

    k_count<<<(N_NODES + 255) / 256, 256>>>(batch, (const int*)pB64);
    k_pool<<<dim3(64, 2), 224>>>(batch, (const int*)pB64);
    k_out<<<dim3(NGRAPH, 2), 128>>>(W_out, b_out, out, out_size);
}

// round 13
// speedup vs baseline: 1.0752x; 1.0752x over previous
#include <cuda_runtime.h>
#include <cuda_bf16.h>
#include <cuda_fp8.h>

#define N_NODES 8192
#define N_EDGES 131072
#define FEAT    512
#define HID     256
#define OUTD    1792     // (2^(K+1)-1)*HID
#define NGRAPH  64
#define WORDS   256      // 8192 / 32 bits
#define A1CAP   128      // per-row 1-hop cap (max degree ~45)
#define A2CAP   1536     // per-row 2-hop cap (max ~400)
#define ROWB    (OUTD * 2)   // bytes per bf16 mirror row
#define FP8SCL  16.0f        // exponent shift into e4m3 normal range

// ---------------- device scratch (no allocations allowed) ----------------
__device__ unsigned g_Abit [N_NODES * WORDS];   // raw binarized adjacency (8 MB)
__device__ int      g_selfcnt[N_NODES];
__device__ float    g_dinv1[N_NODES];
__device__ float    g_dinv2[N_NODES];
__device__ int      g_idx1[N_NODES * A1CAP];    // A1 CSR, BYTE offsets (bf16 rows)
__device__ int      g_cnt1[N_NODES];
__device__ int      g_idx2[(size_t)N_NODES * A2CAP];   // A2 CSR, byte offsets (fp8 rows)
__device__ int      g_cnt2[N_NODES];
__device__ float    g_h[(size_t)N_NODES * OUTD];           // fp32 h_node (56 MB)
__device__ __nv_bfloat16 g_hb1[(size_t)N_NODES * OUTD];    // bf16 dinv1-scaled (A1 gathers)
__device__ unsigned char g_hb2[(size_t)N_NODES * OUTD];    // e4m3 16*dinv2-scaled (A2 gathers)
__device__ float    g_pool[NGRAPH * OUTD];
__device__ int      g_gcnt[NGRAPH];
__device__ int      g_e64, g_b64;               // truthy => int64 layout

__device__ __forceinline__ int geti(const void* p, int i, int is64) {
    return is64 ? (int)((const long long*)p)[i] : ((const int*)p)[i];
}

__device__ __forceinline__ float2 fp8x2_to_float2(unsigned short s) {
    __half2_raw hr = __nv_cvt_fp8x2_to_halfraw2(s, __NV_E4M3);
    return __half22float2(*reinterpret_cast<__half2*>(&hr));
}
__device__ __forceinline__ unsigned short float2_to_fp8x2(float a, float b) {
    return __nv_cvt_float2_to_fp8x2(make_float2(a, b), __NV_SATFINITE, __NV_E4M3);
}

// ---------------- dtype detection (parallel) ----------------
__global__ void k_detect(const int* __restrict__ w, int nwords, int* flag) {
    int stride = 2 * gridDim.x * blockDim.x;
    int any = 0;
    for (int k = 1 + 2 * (int)(blockIdx.x * blockDim.x + threadIdx.x);
         k < nwords; k += stride)
        any |= w[k];
    if (__syncthreads_or(any) && threadIdx.x == 0)
        atomicAnd(flag, 0);
}

// ---------------- build raw adjacency bitmask ----------------
__global__ void k_edges(const void* __restrict__ e, const int* __restrict__ e64flag) {
    int i = blockIdx.x * blockDim.x + threadIdx.x;
    if (i >= N_EDGES) return;
    int is64 = *e64flag;
    int r = geti(e, i, is64);
    int c = geti(e, N_EDGES + i, is64);
    atomicOr(&g_Abit[r * WORDS + (c >> 5)], 1u << (c & 31));
    if (r == c) atomicAdd(&g_selfcnt[r], 1);
}

// Warp-shuffle block scan over per-word popcounts; extract set bits (ascending)
// scaled by mult. 2 barriers per call.
__device__ __forceinline__ int scan_extract(unsigned m, int t, int* s_warp,
                                            int* dst, int cap, int mult, int* tot) {
    int lane = t & 31, wid = t >> 5;
    int pc = __popc(m);
    int x = pc;
#pragma unroll
    for (int off = 1; off < 32; off <<= 1) {
        int v = __shfl_up_sync(0xffffffffu, x, off);
        if (lane >= off) x += v;
    }
    if (lane == 31) s_warp[wid] = x;
    __syncthreads();
    int base = 0, total = 0;
#pragma unroll
    for (int w = 0; w < 8; w++) {
        int s = s_warp[w];
        if (w < wid) base += s;
        total += s;
    }
    int o = base + x - pc;
    unsigned mm = m;
    while (mm) {
        int b = __ffs(mm) - 1; mm &= mm - 1;
        if (o < cap) dst[o] = (t * 32 + b) * mult;
        o++;
    }
    __syncthreads();
    *tot = total;
    return total < cap ? total : cap;
}

// ---------------- A2 build + CSR (byte offsets) + degrees ----------------
__global__ __launch_bounds__(256) void k_a2() {
    int i = blockIdx.x, t = threadIdx.x;
    __shared__ int   s_warp[8];
    __shared__ int   s_raw[128];
    __shared__ uint4 s_acc[4][64];
    __shared__ int   s_diag;

    unsigned w = g_Abit[i * WORDS + t];
    int tot_raw;
    int cnt_raw = scan_extract(w, t, s_warp, s_raw, 128, 1, &tot_raw);

    // neighbor-OR with uint4 loads: subgroup sg handles neighbors sg, sg+4, ...
    // over its 16-byte word slice wg.  (measured win vs scalar OR)
    int wg = t & 63, sg = t >> 6;
    uint4 acc4 = make_uint4(0, 0, 0, 0);
    for (int n = sg; n < cnt_raw; n += 4) {
        uint4 v = *(const uint4*)&g_Abit[s_raw[n] * WORDS + wg * 4];
        acc4.x |= v.x; acc4.y |= v.y; acc4.z |= v.z; acc4.w |= v.w;
    }
    s_acc[sg][wg] = acc4;
    __syncthreads();
    const unsigned* flat = (const unsigned*)&s_acc[0][0];
    unsigned accw = flat[t] | flat[256 + t] | flat[512 + t] | flat[768 + t];

    unsigned dm = (t == (i >> 5)) ? (1u << (i & 31)) : 0u;
    unsigned a2 = accw & ~w & ~dm;

    // diagonal removal rule for A1: (A - I) > 0 keeps diag only if selfcnt >= 2
    if (t == (i >> 5))
        s_diag = ((w & (1u << (i & 31))) && g_selfcnt[i] < 2) ? 1 : 0;
    __syncthreads();
    int remove = s_diag;

    // A1 CSR directly from the raw neighbor list
    if (t < cnt_raw) {
        int j = s_raw[t];
        int pos = t;
        if (remove) {
            if (j == i) pos = -1;
            else if (j > i) pos = t - 1;
        }
        if (pos >= 0 && pos < A1CAP)
            g_idx1[i * A1CAP + pos] = j * ROWB;
    }
    int tot1 = tot_raw - remove;

    int tot2;
    int c2 = scan_extract(a2, t, s_warp, &g_idx2[(size_t)i * A2CAP], A2CAP, OUTD, &tot2);

    if (t == 0) {
        g_cnt1[i] = tot1 < A1CAP ? tot1 : A1CAP;
        g_cnt2[i] = c2;
        g_dinv1[i] = tot1 > 0 ? rsqrtf((float)tot1) : 0.f;
        g_dinv2[i] = tot2 > 0 ? rsqrtf((float)tot2) : 0.f;
    }
}

// ---------------- embed: r = relu(x @ w_embed) -> g_h / scaled mirrors ----------------
// 128x128 tile, BK=32, 256 threads, 8x8 per thread.
__global__ __launch_bounds__(256) void k_embed(const float* __restrict__ X,
                                               const float* __restrict__ W) {
    __shared__ float As[32][128 + 4];
    __shared__ float Bs[32][128 + 4];
    int bm = blockIdx.x * 128;
    int bn = blockIdx.y * 128;
    int tid = threadIdx.x;
    int tr = tid >> 4, tc = tid & 15;
    float acc[8][8] = {};
    for (int k0 = 0; k0 < FEAT; k0 += 32) {
#pragma unroll
        for (int q = 0; q < 4; q++) {
            int idx = tid * 4 + q;
            int m  = idx >> 3;
            int kg = (idx & 7) * 4;
            float4 v = *(const float4*)(X + (size_t)(bm + m) * FEAT + k0 + kg);
            As[kg + 0][m] = v.x; As[kg + 1][m] = v.y;
            As[kg + 2][m] = v.z; As[kg + 3][m] = v.w;
        }
#pragma unroll
        for (int q = 0; q < 4; q++) {
            int idx = tid * 4 + q;
            int k  = idx >> 5;
            int ng = (idx & 31) * 4;
            float4 v = *(const float4*)(W + (size_t)(k0 + k) * HID + bn + ng);
            *(float4*)&Bs[k][ng] = v;
        }
        __syncthreads();
#pragma unroll
        for (int kk = 0; kk < 32; kk++) {
            float a[8], b[8];
#pragma unroll
            for (int p = 0; p < 8; p++) a[p] = As[kk][tr * 8 + p];
#pragma unroll
            for (int q = 0; q < 8; q++) b[q] = Bs[kk][tc * 8 + q];
#pragma unroll
            for (int p = 0; p < 8; p++)
#pragma unroll
                for (int q = 0; q < 8; q++)
                    acc[p][q] += a[p] * b[q];
        }
        __syncthreads();
    }
#pragma unroll
    for (int p = 0; p < 8; p++) {
        int row = bm + tr * 8 + p;
        float d1 = g_dinv1[row];
        float s2 = FP8SCL * g_dinv2[row];
        size_t o = (size_t)row * OUTD + bn + tc * 8;
        float r[8];
#pragma unroll
        for (int q = 0; q < 8; q++) {
            float v = acc[p][q];
            r[q] = v > 0.f ? v : 0.f;
            g_h[o + q]   = r[q];
            g_hb1[o + q] = __float2bfloat16_rn(d1 * r[q]);
        }
        uint2 m2;
        m2.x = (unsigned)float2_to_fp8x2(s2 * r[0], s2 * r[1])
             | ((unsigned)float2_to_fp8x2(s2 * r[2], s2 * r[3]) << 16);
        m2.y = (unsigned)float2_to_fp8x2(s2 * r[4], s2 * r[5])
             | ((unsigned)float2_to_fp8x2(s2 * r[6], s2 * r[7]) << 16);
        *(uint2*)&g_hb2[o] = m2;
    }
}

// ---------------- SpMM from CSR: 8 cols/thread, smem-staged offsets ----------------
// grid (N_NODES, 2): y=0 -> A1 (bf16 LDG.128), y=1 -> A2 (fp8 LDG.64).
__global__ void k_spmm(int in_off, int out_off1, int out_off2, int write_mirror) {
    int i = blockIdx.x, t = threadIdx.x, y = blockIdx.y;
    __shared__ int s_off[A2CAP];

    float a0[8] = {}, a1[8] = {}, a2[8] = {}, a3[8] = {};
    float di;
    int out_off;

    if (y == 0) {          // ---- A1: bf16 gathers ----
        const int* idx = &g_idx1[i * A1CAP];
        int cnt = g_cnt1[i];
        di  = g_dinv1[i];
        out_off = out_off1;
        for (int k = t; k < cnt; k += blockDim.x)
            s_off[k] = idx[k];
        __syncthreads();
        const char* base = (const char*)g_hb1 + 2 * in_off + 16 * t;
        int n = 0;
        for (; n + 3 < cnt; n += 4) {
            uint4 u0 = *(const uint4*)(base + s_off[n + 0]);
            uint4 u1 = *(const uint4*)(base + s_off[n + 1]);
            uint4 u2 = *(const uint4*)(base + s_off[n + 2]);
            uint4 u3 = *(const uint4*)(base + s_off[n + 3]);
#pragma unroll
            for (int q = 0; q < 4; q++) {
                float2 v; unsigned w;
                w = (&u0.x)[q]; v = __bfloat1622float2(*reinterpret_cast<__nv_bfloat162*>(&w));
                a0[2 * q] += v.x; a0[2 * q + 1] += v.y;
                w = (&u1.x)[q]; v = __bfloat1622float2(*reinterpret_cast<__nv_bfloat162*>(&w));
                a1[2 * q] += v.x; a1[2 * q + 1] += v.y;
                w = (&u2.x)[q]; v = __bfloat1622float2(*reinterpret_cast<__nv_bfloat162*>(&w));
                a2[2 * q] += v.x; a2[2 * q + 1] += v.y;
                w = (&u3.x)[q]; v = __bfloat1622float2(*reinterpret_cast<__nv_bfloat162*>(&w));
                a3[2 * q] += v.x; a3[2 * q + 1] += v.y;
            }
        }
        for (; n < cnt; n++) {
            uint4 u = *(const uint4*)(base + s_off[n]);
#pragma unroll
            for (int q = 0; q < 4; q++) {
                unsigned w = (&u.x)[q];
                float2 v = __bfloat1622float2(*reinterpret_cast<__nv_bfloat162*>(&w));
                a0[2 * q] += v.x; a0[2 * q + 1] += v.y;
            }
        }
    } else {               // ---- A2: fp8 gathers ----
        const int* idx = &g_idx2[(size_t)i * A2CAP];
        int cnt = g_cnt2[i];
        di  = g_dinv2[i] * (1.0f / FP8SCL);
        out_off = out_off2;
        for (int k = t; k < cnt; k += blockDim.x)
            s_off[k] = idx[k];
        __syncthreads();
        const char* base = (const char*)g_hb2 + in_off + 8 * t;
        int n = 0;
        for (; n + 7 < cnt; n += 8) {
            uint2 u0 = *(const uint2*)(base + s_off[n + 0]);
            uint2 u1 = *(const uint2*)(base + s_off[n + 1]);
            uint2 u2 = *(const uint2*)(base + s_off[n + 2]);
            uint2 u3 = *(const uint2*)(base + s_off[n + 3]);
            uint2 u4 = *(const uint2*)(base + s_off[n + 4]);
            uint2 u5 = *(const uint2*)(base + s_off[n + 5]);
            uint2 u6 = *(const uint2*)(base + s_off[n + 6]);
            uint2 u7 = *(const uint2*)(base + s_off[n + 7]);
#pragma unroll
            for (int q = 0; q < 2; q++) {
                unsigned w; float2 v;
                w = (&u0.x)[q];
                v = fp8x2_to_float2((unsigned short)w);
                a0[4 * q] += v.x; a0[4 * q + 1] += v.y;
                v = fp8x2_to_float2((unsigned short)(w >> 16));
                a0[4 * q + 2] += v.x; a0[4 * q + 3] += v.y;
                w = (&u1.x)[q];
                v = fp8x2_to_float2((unsigned short)w);
                a1[4 * q] += v.x; a1[4 * q + 1] += v.y;
                v = fp8x2_to_float2((unsigned short)(w >> 16));
                a1[4 * q + 2] += v.x; a1[4 * q + 3] += v.y;
                w = (&u2.x)[q];
                v = fp8x2_to_float2((unsigned short)w);
                a2[4 * q] += v.x; a2[4 * q + 1] += v.y;
                v = fp8x2_to_float2((unsigned short)(w >> 16));
                a2[4 * q + 2] += v.x; a2[4 * q + 3] += v.y;
                w = (&u3.x)[q];
                v = fp8x2_to_float2((unsigned short)w);
                a3[4 * q] += v.x; a3[4 * q + 1] += v.y;
                v = fp8x2_to_float2((unsigned short)(w >> 16));
                a3[4 * q + 2] += v.x; a3[4 * q + 3] += v.y;
                w = (&u4.x)[q];
                v = fp8x2_to_float2((unsigned short)w);
                a0[4 * q] += v.x; a0[4 * q + 1] += v.y;
                v = fp8x2_to_float2((unsigned short)(w >> 16));
                a0[4 * q + 2] += v.x; a0[4 * q + 3] += v.y;
                w = (&u5.x)[q];
                v = fp8x2_to_float2((unsigned short)w);
                a1[4 * q] += v.x; a1[4 * q + 1] += v.y;
                v = fp8x2_to_float2((unsigned short)(w >> 16));
                a1[4 * q + 2] += v.x; a1[4 * q + 3] += v.y;
                w = (&u6.x)[q];
                v = fp8x2_to_float2((unsigned short)w);
                a2[4 * q] += v.x; a2[4 * q + 1] += v.y;
                v = fp8x2_to_float2((unsigned short)(w >> 16));
                a2[4 * q + 2] += v.x; a2[4 * q + 3] += v.y;
                w = (&u7.x)[q];
                v = fp8x2_to_float2((unsigned short)w);
                a3[4 * q] += v.x; a3[4 * q + 1] += v.y;
                v = fp8x2_to_float2((unsigned short)(w >> 16));
                a3[4 * q + 2] += v.x; a3[4 * q + 3] += v.y;
            }
        }
        for (; n < cnt; n++) {
            uint2 u = *(const uint2*)(base + s_off[n]);
#pragma unroll
            for (int q = 0; q < 2; q++) {
                unsigned w = (&u.x)[q];
                float2 v = fp8x2_to_float2((unsigned short)w);
                a0[4 * q] += v.x; a0[4 * q + 1] += v.y;
                v = fp8x2_to_float2((unsigned short)(w >> 16));
                a0[4 * q + 2] += v.x; a0[4 * q + 3] += v.y;
            }
        }
    }

    float r[8];
#pragma unroll
    for (int q = 0; q < 8; q++) {
        float v = di * ((a0[q] + a1[q]) + (a2[q] + a3[q]));
        r[q] = v > 0.f ? v : 0.f;
    }
    size_t ob = (size_t)i * OUTD + out_off + 8 * t;
    *(float4*)&g_h[ob]     = make_float4(r[0], r[1], r[2], r[3]);
    *(float4*)&g_h[ob + 4] = make_float4(r[4], r[5], r[6], r[7]);
    if (write_mirror) {
        float d1 = g_dinv1[i];
        float s2 = FP8SCL * g_dinv2[i];
        uint4 m1;
#pragma unroll
        for (int q = 0; q < 4; q++) {
            __nv_bfloat162 b1 = __float22bfloat162_rn(
                make_float2(d1 * r[2 * q], d1 * r[2 * q + 1]));
            (&m1.x)[q] = *reinterpret_cast<unsigned*>(&b1);
        }
        *(uint4*)&g_hb1[ob] = m1;
        uint2 m2;
        m2.x = (unsigned)float2_to_fp8x2(s2 * r[0], s2 * r[1])
             | ((unsigned)float2_to_fp8x2(s2 * r[2], s2 * r[3]) << 16);
        m2.y = (unsigned)float2_to_fp8x2(s2 * r[4], s2 * r[5])
             | ((unsigned)float2_to_fp8x2(s2 * r[6], s2 * r[7]) << 16);
        *(uint2*)&g_hb2[ob] = m2;
    }
}

// ---------------- graph sizes ----------------
__global__ void k_count(const void* __restrict__ batch, const int* __restrict__ b64flag) {
    int i = blockIdx.x * blockDim.x + threadIdx.x;
    if (i < N_NODES) atomicAdd(&g_gcnt[geti(batch, i, *b64flag)], 1);
}

// ---------------- segment-sum pool (batch is sorted), float4 ----------------
__global__ __launch_bounds__(224) void k_pool(const void* __restrict__ batch,
                                              const int* __restrict__ b64flag) {
    int is64 = *b64flag;
    int n0 = blockIdx.x * 128;
    int c  = (blockIdx.y * 224 + threadIdx.x) * 4;
    float4 acc = {0.f, 0.f, 0.f, 0.f};
    int cur = geti(batch, n0, is64);
    for (int n = n0; n < n0 + 128; n++) {
        int b = geti(batch, n, is64);
        if (b != cur) {
            float* p = &g_pool[cur * OUTD + c];
            atomicAdd(p + 0, acc.x); atomicAdd(p + 1, acc.y);
            atomicAdd(p + 2, acc.z); atomicAdd(p + 3, acc.w);
            acc = make_float4(0.f, 0.f, 0.f, 0.f);
            cur = b;
        }
        float4 v = *(const float4*)&g_h[(size_t)n * OUTD + c];
        acc.x += v.x; acc.y += v.y; acc.z += v.z; acc.w += v.w;
    }
    float* p = &g_pool[cur * OUTD + c];
    atomicAdd(p + 0, acc.x); atomicAdd(p + 1, acc.y);
    atomicAdd(p + 2, acc.z); atomicAdd(p + 3, acc.w);
}

// ---------------- final: (pool/cnt) @ W_out + b_out ; tail = loss = 0 ----------------
// grid (NGRAPH, 2), 128 threads: each block computes 128 output columns.
__global__ __launch_bounds__(128) void k_out(const float* __restrict__ Wout,
                                             const float* __restrict__ bout,
                                             float* __restrict__ out, int out_size) {
    int g = blockIdx.x, t = threadIdx.x;
    int h = blockIdx.y * 128 + t;
    __shared__ float sg[OUTD];
    float inv = 1.0f / fmaxf((float)g_gcnt[g], 1.0f);
    for (int k = t; k < OUTD; k += 128)
        sg[k] = g_pool[g * OUTD + k] * inv;
    __syncthreads();
    float acc = bout[h];
#pragma unroll 8
    for (int k = 0; k < OUTD; k++)
        acc += sg[k] * Wout[(size_t)k * HID + h];
    int oi = g * HID + h;
    if (oi < out_size) out[oi] = acc;
    if (g == 0 && blockIdx.y == 0) {
        for (int idx = NGRAPH * HID + t; idx < out_size; idx += 128)
            out[idx] = 0.f;
    }
}

// ---------------- launcher ----------------
extern "C" void kernel_launch(void* const* d_in, const int* in_sizes, int n_in,
                              void* d_out, int out_size) {
    const float* x       = (const float*)d_in[0];
    const void*  e       = d_in[1];
    const void*  batch   = d_in[2];
    const float* w_embed = (const float*)d_in[3];
    const float* W_out   = (const float*)d_in[4];
    const float* b_out   = (const float*)d_in[5];
    float* out = (float*)d_out;

    void *pA, *pSelf, *pPool, *pGcnt, *pE64, *pB64;
    cudaGetSymbolAddress(&pA,    g_Abit);
    cudaGetSymbolAddress(&pSelf, g_selfcnt);
    cudaGetSymbolAddress(&pPool, g_pool);
    cudaGetSymbolAddress(&pGcnt, g_gcnt);
    cudaGetSymbolAddress(&pE64,  g_e64);
    cudaGetSymbolAddress(&pB64,  g_b64);

    cudaMemsetAsync(pA,    0, sizeof(unsigned) * N_NODES * WORDS);
    cudaMemsetAsync(pSelf, 0, sizeof(int)   * N_NODES);
    cudaMemsetAsync(pPool, 0, sizeof(float) * NGRAPH * OUTD);
    cudaMemsetAsync(pGcnt, 0, sizeof(int)   * NGRAPH);
    cudaMemsetAsync(pE64,  1, sizeof(int));   // truthy "int64" default
    cudaMemsetAsync(pB64,  1, sizeof(int));

    k_detect<<<64, 256>>>((const int*)e,     2 * N_EDGES, (int*)pE64);
    k_detect<<<64, 256>>>((const int*)batch, N_NODES,     (int*)pB64);

    k_edges<<<(N_EDGES + 255) / 256, 256>>>(e, (const int*)pE64);
    k_a2<<<N_NODES, 256>>>();
    k_embed<<<dim3(N_NODES / 128, HID / 128), 256>>>(x, w_embed);

    // hop 1: in = cols [0,256) -> A1 out [256,512), A2 out [512,768)
    k_spmm<<<dim3(N_NODES, 2), HID / 8>>>(0, HID, 2 * HID, 1);
    // hop 2: in = cols [256,768) -> A1 out [768,1280), A2 out [1280,1792)
    k_spmm<<<dim3(N_NODES, 2), 2 * HID / 8>>>(HID, 3 * HID, 5 * HID, 0);

    k_count<<<(N_NODES + 255) / 256, 256>>>(batch, (const int*)pB64);
    k_pool<<<dim3(64, 2), 224>>>(batch, (const int*)pB64);
    k_out<<<dim3(NGRAPH, 2), 128>>>(W_out, b_out, out, out_size);
}

// round 14
// speedup vs baseline: 1.3521x; 1.2576x over previous
#include <cuda_runtime.h>
#include <cuda_bf16.h>
#include <cuda_fp8.h>

#define N_NODES 8192
#define N_EDGES 131072
#define FEAT    512
#define HID     256
#define OUTD    1792     // (2^(K+1)-1)*HID
#define NGRAPH  64
#define WORDS   256      // 8192 / 32 bits
#define A1CAP   128      // per-row 1-hop cap (max degree ~45)
#define A2CAP   1536     // per-row 2-hop cap (max ~400)
#define ROWB    (OUTD * 2)   // bytes per bf16 mirror row
#define FP8SCL  16.0f        // exponent shift into e4m3 normal range

// ---------------- device scratch (no allocations allowed) ----------------
__device__ unsigned g_Abit [N_NODES * WORDS];   // raw binarized adjacency (8 MB)
__device__ int      g_selfcnt[N_NODES];
__device__ float    g_dinv1[N_NODES];
__device__ float    g_dinv2[N_NODES];
__device__ int      g_idx1[N_NODES * A1CAP];    // A1 CSR, BYTE offsets (bf16 rows)
__device__ int      g_cnt1[N_NODES];
__device__ int      g_idx2[(size_t)N_NODES * A2CAP];   // A2 CSR, byte offsets (fp8 rows)
__device__ int      g_cnt2[N_NODES];
__device__ float    g_h[(size_t)N_NODES * OUTD];           // fp32 h_node (56 MB)
__device__ __nv_bfloat16 g_hb1[(size_t)N_NODES * OUTD];    // bf16 dinv1-scaled (A1 gathers)
__device__ unsigned char g_hb2[(size_t)N_NODES * OUTD];    // e4m3 16*dinv2-scaled (A2 gathers)
__device__ float    g_pool[NGRAPH * OUTD];
__device__ int      g_gcnt[NGRAPH];
__device__ int      g_e64, g_b64;               // truthy => int64 layout

__device__ __forceinline__ int geti(const void* p, int i, int is64) {
    return is64 ? (int)((const long long*)p)[i] : ((const int*)p)[i];
}

__device__ __forceinline__ float2 fp8x2_to_float2(unsigned short s) {
    __half2_raw hr = __nv_cvt_fp8x2_to_halfraw2(s, __NV_E4M3);
    return __half22float2(*reinterpret_cast<__half2*>(&hr));
}
__device__ __forceinline__ unsigned short float2_to_fp8x2(float a, float b) {
    return __nv_cvt_float2_to_fp8x2(make_float2(a, b), __NV_SATFINITE, __NV_E4M3);
}

// ---------------- dtype detection (parallel) ----------------
// flag pre-set truthy (0x01010101). Any nonzero odd 32-bit word -> int32 layout
// -> flag := 0. Deterministic regardless of block order.
__global__ void k_detect(const int* __restrict__ w, int nwords, int* flag) {
    int stride = 2 * gridDim.x * blockDim.x;
    int any = 0;
    for (int k = 1 + 2 * (int)(blockIdx.x * blockDim.x + threadIdx.x);
         k < nwords; k += stride)
        any |= w[k];
    if (__syncthreads_or(any) && threadIdx.x == 0)
        atomicAnd(flag, 0);
}

// ---------------- build raw adjacency bitmask ----------------
__global__ void k_edges(const void* __restrict__ e, const int* __restrict__ e64flag) {
    int i = blockIdx.x * blockDim.x + threadIdx.x;
    if (i >= N_EDGES) return;
    int is64 = *e64flag;
    int r = geti(e, i, is64);
    int c = geti(e, N_EDGES + i, is64);
    atomicOr(&g_Abit[r * WORDS + (c >> 5)], 1u << (c & 31));
    if (r == c) atomicAdd(&g_selfcnt[r], 1);
}

// Warp-shuffle block scan over per-word popcounts; extract set bits (ascending)
// scaled by mult. 2 barriers per call.
__device__ __forceinline__ int scan_extract(unsigned m, int t, int* s_warp,
                                            int* dst, int cap, int mult, int* tot) {
    int lane = t & 31, wid = t >> 5;
    int pc = __popc(m);
    int x = pc;
#pragma unroll
    for (int off = 1; off < 32; off <<= 1) {
        int v = __shfl_up_sync(0xffffffffu, x, off);
        if (lane >= off) x += v;
    }
    if (lane == 31) s_warp[wid] = x;
    __syncthreads();
    int base = 0, total = 0;
#pragma unroll
    for (int w = 0; w < 8; w++) {
        int s = s_warp[w];
        if (w < wid) base += s;
        total += s;
    }
    int o = base + x - pc;
    unsigned mm = m;
    while (mm) {
        int b = __ffs(mm) - 1; mm &= mm - 1;
        if (o < cap) dst[o] = (t * 32 + b) * mult;
        o++;
    }
    __syncthreads();
    *tot = total;
    return total < cap ? total : cap;
}

// ---------------- A2 build + CSR (byte offsets) + degrees ----------------
__global__ __launch_bounds__(256) void k_a2() {
    int i = blockIdx.x, t = threadIdx.x;
    __shared__ int s_warp[8];
    __shared__ int s_raw[128];
    __shared__ int s_diag;

    unsigned w = g_Abit[i * WORDS + t];
    int tot_raw;
    int cnt_raw = scan_extract(w, t, s_warp, s_raw, 128, 1, &tot_raw);

    unsigned acc = 0;
    for (int n = 0; n < cnt_raw; n++)
        acc |= g_Abit[s_raw[n] * WORDS + t];

    unsigned dm = (t == (i >> 5)) ? (1u << (i & 31)) : 0u;
    unsigned a2 = acc & ~w & ~dm;

    // diagonal removal rule for A1: (A - I) > 0 keeps diag only if selfcnt >= 2
    if (t == (i >> 5))
        s_diag = ((w & (1u << (i & 31))) && g_selfcnt[i] < 2) ? 1 : 0;
    __syncthreads();
    int remove = s_diag;

    // A1 CSR directly from the raw neighbor list (skip re-scan)
    if (t < cnt_raw) {
        int j = s_raw[t];
        int pos = t;
        if (remove) {
            if (j == i) pos = -1;
            else if (j > i) pos = t - 1;
        }
        if (pos >= 0 && pos < A1CAP)
            g_idx1[i * A1CAP + pos] = j * ROWB;
    }
    int tot1 = tot_raw - remove;

    int tot2;
    int c2 = scan_extract(a2, t, s_warp, &g_idx2[(size_t)i * A2CAP], A2CAP, OUTD, &tot2);

    if (t == 0) {
        g_cnt1[i] = tot1 < A1CAP ? tot1 : A1CAP;
        g_cnt2[i] = c2;
        g_dinv1[i] = tot1 > 0 ? rsqrtf((float)tot1) : 0.f;
        g_dinv2[i] = tot2 > 0 ? rsqrtf((float)tot2) : 0.f;
    }
}

// ---------------- embed: r = relu(x @ w_embed) -> g_h / scaled mirrors ----------------
// 128x128 tile, BK=32, 256 threads, 8x8 per thread.
__global__ __launch_bounds__(256) void k_embed(const float* __restrict__ X,
                                               const float* __restrict__ W) {
    __shared__ float As[32][128 + 4];
    __shared__ float Bs[32][128 + 4];
    int bm = blockIdx.x * 128;
    int bn = blockIdx.y * 128;
    int tid = threadIdx.x;
    int tr = tid >> 4, tc = tid & 15;
    float acc[8][8] = {};
    for (int k0 = 0; k0 < FEAT; k0 += 32) {
#pragma unroll
        for (int q = 0; q < 4; q++) {
            int idx = tid * 4 + q;
            int m  = idx >> 3;
            int kg = (idx & 7) * 4;
            float4 v = *(const float4*)(X + (size_t)(bm + m) * FEAT + k0 + kg);
            As[kg + 0][m] = v.x; As[kg + 1][m] = v.y;
            As[kg + 2][m] = v.z; As[kg + 3][m] = v.w;
        }
#pragma unroll
        for (int q = 0; q < 4; q++) {
            int idx = tid * 4 + q;
            int k  = idx >> 5;
            int ng = (idx & 31) * 4;
            float4 v = *(const float4*)(W + (size_t)(k0 + k) * HID + bn + ng);
            *(float4*)&Bs[k][ng] = v;
        }
        __syncthreads();
#pragma unroll
        for (int kk = 0; kk < 32; kk++) {
            float a[8], b[8];
#pragma unroll
            for (int p = 0; p < 8; p++) a[p] = As[kk][tr * 8 + p];
#pragma unroll
            for (int q = 0; q < 8; q++) b[q] = Bs[kk][tc * 8 + q];
#pragma unroll
            for (int p = 0; p < 8; p++)
#pragma unroll
                for (int q = 0; q < 8; q++)
                    acc[p][q] += a[p] * b[q];
        }
        __syncthreads();
    }
#pragma unroll
    for (int p = 0; p < 8; p++) {
        int row = bm + tr * 8 + p;
        float d1 = g_dinv1[row];
        float s2 = FP8SCL * g_dinv2[row];
        size_t o = (size_t)row * OUTD + bn + tc * 8;
        float r[8];
#pragma unroll
        for (int q = 0; q < 8; q++) {
            float v = acc[p][q];
            r[q] = v > 0.f ? v : 0.f;
            g_h[o + q]   = r[q];
            g_hb1[o + q] = __float2bfloat16_rn(d1 * r[q]);
        }
        uint2 m2;
        m2.x = (unsigned)float2_to_fp8x2(s2 * r[0], s2 * r[1])
             | ((unsigned)float2_to_fp8x2(s2 * r[2], s2 * r[3]) << 16);
        m2.y = (unsigned)float2_to_fp8x2(s2 * r[4], s2 * r[5])
             | ((unsigned)float2_to_fp8x2(s2 * r[6], s2 * r[7]) << 16);
        *(uint2*)&g_hb2[o] = m2;
    }
}

// ---------------- SpMM from CSR: 8 cols/thread ----------------
// grid (N_NODES, 2): y=0 -> A1 (bf16 LDG.128), y=1 -> A2 (fp8 LDG.64).
__global__ void k_spmm(int in_off, int out_off1, int out_off2, int write_mirror) {
    int i = blockIdx.x, t = threadIdx.x, y = blockIdx.y;
    __shared__ int s_off[A2CAP];

    float a0[8] = {}, a1[8] = {}, a2[8] = {}, a3[8] = {};
    float di;
    int out_off;

    if (y == 0) {          // ---- A1: bf16 gathers ----
        const int* idx = &g_idx1[i * A1CAP];
        int cnt = g_cnt1[i];
        di  = g_dinv1[i];
        out_off = out_off1;
        for (int k = t; k < cnt; k += blockDim.x)
            s_off[k] = idx[k];
        __syncthreads();
        const char* base = (const char*)g_hb1 + 2 * in_off + 16 * t;
        int n = 0;
        for (; n + 3 < cnt; n += 4) {
            uint4 u0 = *(const uint4*)(base + s_off[n + 0]);
            uint4 u1 = *(const uint4*)(base + s_off[n + 1]);
            uint4 u2 = *(const uint4*)(base + s_off[n + 2]);
            uint4 u3 = *(const uint4*)(base + s_off[n + 3]);
#pragma unroll
            for (int q = 0; q < 4; q++) {
                float2 v; unsigned w;
                w = (&u0.x)[q]; v = __bfloat1622float2(*reinterpret_cast<__nv_bfloat162*>(&w));
                a0[2 * q] += v.x; a0[2 * q + 1] += v.y;
                w = (&u1.x)[q]; v = __bfloat1622float2(*reinterpret_cast<__nv_bfloat162*>(&w));
                a1[2 * q] += v.x; a1[2 * q + 1] += v.y;
                w = (&u2.x)[q]; v = __bfloat1622float2(*reinterpret_cast<__nv_bfloat162*>(&w));
                a2[2 * q] += v.x; a2[2 * q + 1] += v.y;
                w = (&u3.x)[q]; v = __bfloat1622float2(*reinterpret_cast<__nv_bfloat162*>(&w));
                a3[2 * q] += v.x; a3[2 * q + 1] += v.y;
            }
        }
        for (; n < cnt; n++) {
            uint4 u = *(const uint4*)(base + s_off[n]);
#pragma unroll
            for (int q = 0; q < 4; q++) {
                unsigned w = (&u.x)[q];
                float2 v = __bfloat1622float2(*reinterpret_cast<__nv_bfloat162*>(&w));
                a0[2 * q] += v.x; a0[2 * q + 1] += v.y;
            }
        }
    } else {               // ---- A2: fp8 gathers ----
        const int* idx = &g_idx2[(size_t)i * A2CAP];
        int cnt = g_cnt2[i];
        di  = g_dinv2[i] * (1.0f / FP8SCL);
        out_off = out_off2;
        for (int k = t; k < cnt; k += blockDim.x)
            s_off[k] = idx[k];
        __syncthreads();
        const char* base = (const char*)g_hb2 + in_off + 8 * t;
        int n = 0;
        for (; n + 7 < cnt; n += 8) {
            uint2 u0 = *(const uint2*)(base + s_off[n + 0]);
            uint2 u1 = *(const uint2*)(base + s_off[n + 1]);
            uint2 u2 = *(const uint2*)(base + s_off[n + 2]);
            uint2 u3 = *(const uint2*)(base + s_off[n + 3]);
            uint2 u4 = *(const uint2*)(base + s_off[n + 4]);
            uint2 u5 = *(const uint2*)(base + s_off[n + 5]);
            uint2 u6 = *(const uint2*)(base + s_off[n + 6]);
            uint2 u7 = *(const uint2*)(base + s_off[n + 7]);
#pragma unroll
            for (int q = 0; q < 2; q++) {
                unsigned w; float2 v;
                w = (&u0.x)[q];
                v = fp8x2_to_float2((unsigned short)w);
                a0[4 * q] += v.x; a0[4 * q + 1] += v.y;
                v = fp8x2_to_float2((unsigned short)(w >> 16));
                a0[4 * q + 2] += v.x; a0[4 * q + 3] += v.y;
                w = (&u1.x)[q];
                v = fp8x2_to_float2((unsigned short)w);
                a1[4 * q] += v.x; a1[4 * q + 1] += v.y;
                v = fp8x2_to_float2((unsigned short)(w >> 16));
                a1[4 * q + 2] += v.x; a1[4 * q + 3] += v.y;
                w = (&u2.x)[q];
                v = fp8x2_to_float2((unsigned short)w);
                a2[4 * q] += v.x; a2[4 * q + 1] += v.y;
                v = fp8x2_to_float2((unsigned short)(w >> 16));
                a2[4 * q + 2] += v.x; a2[4 * q + 3] += v.y;
                w = (&u3.x)[q];
                v = fp8x2_to_float2((unsigned short)w);
                a3[4 * q] += v.x; a3[4 * q + 1] += v.y;
                v = fp8x2_to_float2((unsigned short)(w >> 16));
                a3[4 * q + 2] += v.x; a3[4 * q + 3] += v.y;
                w = (&u4.x)[q];
                v = fp8x2_to_float2((unsigned short)w);
                a0[4 * q] += v.x; a0[4 * q + 1] += v.y;
                v = fp8x2_to_float2((unsigned short)(w >> 16));
                a0[4 * q + 2] += v.x; a0[4 * q + 3] += v.y;
                w = (&u5.x)[q];
                v = fp8x2_to_float2((unsigned short)w);
                a1[4 * q] += v.x; a1[4 * q + 1] += v.y;
                v = fp8x2_to_float2((unsigned short)(w >> 16));
                a1[4 * q + 2] += v.x; a1[4 * q + 3] += v.y;
                w = (&u6.x)[q];
                v = fp8x2_to_float2((unsigned short)w);
                a2[4 * q] += v.x; a2[4 * q + 1] += v.y;
                v = fp8x2_to_float2((unsigned short)(w >> 16));
                a2[4 * q + 2] += v.x; a2[4 * q + 3] += v.y;
                w = (&u7.x)[q];
                v = fp8x2_to_float2((unsigned short)w);
                a3[4 * q] += v.x; a3[4 * q + 1] += v.y;
                v = fp8x2_to_float2((unsigned short)(w >> 16));
                a3[4 * q + 2] += v.x; a3[4 * q + 3] += v.y;
            }
        }
        for (; n < cnt; n++) {
            uint2 u = *(const uint2*)(base + s_off[n]);
#pragma unroll
            for (int q = 0; q < 2; q++) {
                unsigned w = (&u.x)[q];
                float2 v = fp8x2_to_float2((unsigned short)w);
                a0[4 * q] += v.x; a0[4 * q + 1] += v.y;
                v = fp8x2_to_float2((unsigned short)(w >> 16));
                a0[4 * q + 2] += v.x; a0[4 * q + 3] += v.y;
            }
        }
    }

    float r[8];
#pragma unroll
    for (int q = 0; q < 8; q++) {
        float v = di * ((a0[q] + a1[q]) + (a2[q] + a3[q]));
        r[q] = v > 0.f ? v : 0.f;
    }
    size_t ob = (size_t)i * OUTD + out_off + 8 * t;
    *(float4*)&g_h[ob]     = make_float4(r[0], r[1], r[2], r[3]);
    *(float4*)&g_h[ob + 4] = make_float4(r[4], r[5], r[6], r[7]);
    if (write_mirror) {
        float d1 = g_dinv1[i];
        float s2 = FP8SCL * g_dinv2[i];
        uint4 m1;
#pragma unroll
        for (int q = 0; q < 4; q++) {
            __nv_bfloat162 b1 = __float22bfloat162_rn(
                make_float2(d1 * r[2 * q], d1 * r[2 * q + 1]));
            (&m1.x)[q] = *reinterpret_cast<unsigned*>(&b1);
        }
        *(uint4*)&g_hb1[ob] = m1;
        uint2 m2;
        m2.x = (unsigned)float2_to_fp8x2(s2 * r[0], s2 * r[1])
             | ((unsigned)float2_to_fp8x2(s2 * r[2], s2 * r[3]) << 16);
        m2.y = (unsigned)float2_to_fp8x2(s2 * r[4], s2 * r[5])
             | ((unsigned)float2_to_fp8x2(s2 * r[6], s2 * r[7]) << 16);
        *(uint2*)&g_hb2[ob] = m2;
    }
}

// ---------------- graph sizes ----------------
__global__ void k_count(const void* __restrict__ batch, const int* __restrict__ b64flag) {
    int i = blockIdx.x * blockDim.x + threadIdx.x;
    if (i < N_NODES) atomicAdd(&g_gcnt[geti(batch, i, *b64flag)], 1);
}

// ---------------- segment-sum pool (batch is sorted), float4 ----------------
__global__ __launch_bounds__(224) void k_pool(const void* __restrict__ batch,
                                              const int* __restrict__ b64flag) {
    int is64 = *b64flag;
    int n0 = blockIdx.x * 128;
    int c  = (blockIdx.y * 224 + threadIdx.x) * 4;
    float4 acc = {0.f, 0.f, 0.f, 0.f};
    int cur = geti(batch, n0, is64);
    for (int n = n0; n < n0 + 128; n++) {
        int b = geti(batch, n, is64);
        if (b != cur) {
            float* p = &g_pool[cur * OUTD + c];
            atomicAdd(p + 0, acc.x); atomicAdd(p + 1, acc.y);
            atomicAdd(p + 2, acc.z); atomicAdd(p + 3, acc.w);
            acc = make_float4(0.f, 0.f, 0.f, 0.f);
            cur = b;
        }
        float4 v = *(const float4*)&g_h[(size_t)n * OUTD + c];
        acc.x += v.x; acc.y += v.y; acc.z += v.z; acc.w += v.w;
    }
    float* p = &g_pool[cur * OUTD + c];
    atomicAdd(p + 0, acc.x); atomicAdd(p + 1, acc.y);
    atomicAdd(p + 2, acc.z); atomicAdd(p + 3, acc.w);
}

// ---------------- final: (pool/cnt) @ W_out + b_out ; tail = loss = 0 ----------------
__global__ __launch_bounds__(256) void k_out(const float* __restrict__ Wout,
                                             const float* __restrict__ bout,
                                             float* __restrict__ out, int out_size) {
    int g = blockIdx.x, h = threadIdx.x;
    __shared__ float sg[OUTD];
    float inv = 1.0f / fmaxf((float)g_gcnt[g], 1.0f);
    for (int k = h; k < OUTD; k += 256)
        sg[k] = g_pool[g * OUTD + k] * inv;
    __syncthreads();
    float acc = bout[h];
    for (int k = 0; k < OUTD; k++)
        acc += sg[k] * Wout[(size_t)k * HID + h];
    int oi = g * HID + h;
    if (oi < out_size) out[oi] = acc;
    if (g == 0) {
        for (int idx = NGRAPH * HID + h; idx < out_size; idx += 256)
            out[idx] = 0.f;
    }
}

// ---------------- launcher ----------------
extern "C" void kernel_launch(void* const* d_in, const int* in_sizes, int n_in,
                              void* d_out, int out_size) {
    const float* x       = (const float*)d_in[0];
    const void*  e       = d_in[1];
    const void*  batch   = d_in[2];
    const float* w_embed = (const float*)d_in[3];
    const float* W_out   = (const float*)d_in[4];
    const float* b_out   = (const float*)d_in[5];
    float* out = (float*)d_out;

    void *pA, *pSelf, *pPool, *pGcnt, *pE64, *pB64;
    cudaGetSymbolAddress(&pA,    g_Abit);
    cudaGetSymbolAddress(&pSelf, g_selfcnt);
    cudaGetSymbolAddress(&pPool, g_pool);
    cudaGetSymbolAddress(&pGcnt, g_gcnt);
    cudaGetSymbolAddress(&pE64,  g_e64);
    cudaGetSymbolAddress(&pB64,  g_b64);

    cudaMemsetAsync(pA,    0, sizeof(unsigned) * N_NODES * WORDS);
    cudaMemsetAsync(pSelf, 0, sizeof(int)   * N_NODES);
    cudaMemsetAsync(pPool, 0, sizeof(float) * NGRAPH * OUTD);
    cudaMemsetAsync(pGcnt, 0, sizeof(int)   * NGRAPH);
    cudaMemsetAsync(pE64,  1, sizeof(int));   // truthy "int64" default
    cudaMemsetAsync(pB64,  1, sizeof(int));

    k_detect<<<64, 256>>>((const int*)e,     2 * N_EDGES, (int*)pE64);
    k_detect<<<64, 256>>>((const int*)batch, N_NODES,     (int*)pB64);

    k_edges<<<(N_EDGES + 255) / 256, 256>>>(e, (const int*)pE64);
    k_a2<<<N_NODES, 256>>>();
    k_embed<<<dim3(N_NODES / 128, HID / 128), 256>>>(x, w_embed);

    // hop 1: in = cols [0,256) -> A1 out [256,512), A2 out [512,768)
    k_spmm<<<dim3(N_NODES, 2), HID / 8>>>(0, HID, 2 * HID, 1);
    // hop 2: in = cols [256,768) -> A1 out [768,1280), A2 out [1280,1792)
    k_spmm<<<dim3(N_NODES, 2), 2 * HID / 8>>>(HID, 3 * HID, 5 * HID, 0);

    k_count<<<(N_NODES + 255) / 256, 256>>>(batch, (const int*)pB64);
    k_pool<<<dim3(64, 2), 224>>>(batch, (const int*)pB64);
    k_out<<<NGRAPH, HID>>>(W_out, b_out, out, out_size);
}